// round 1
// baseline (speedup 1.0000x reference)
#include <cuda_runtime.h>
#include <math.h>

// Problem constants (B=4, S=4096, D=2048, ND=64, E=3)
#define T_TOK 16384
#define DDIM  2048
#define DHALF 1024
#define ND    64
#define NE    3
#define LN_EPS 1e-5f

// -------- device scratch (no allocation allowed) --------
__device__ float g_H[(size_t)T_TOK * DDIM];     // cls|var hidden, later reused as dh_sorted
__device__ float g_do[(size_t)T_TOK * DDIM];    // decoder pre-LN output (sorted order)
__device__ float g_noise[(size_t)T_TOK * ND];   // noise in sorted order
__device__ float g_strength[T_TOK];
__device__ int   g_sel[T_TOK];
__device__ int   g_idx[T_TOK];                  // sorted position -> original token
__device__ int   g_cnt[NE];
__device__ int   g_cur[NE];
__device__ int   g_off[NE + 1];

__device__ __forceinline__ float siluf(float v) { return v / (1.f + expf(-v)); }

// ===================== init / scan / scatter =====================
__global__ void init_kernel() {
    int i = threadIdx.x;
    if (i < NE) { g_cnt[i] = 0; g_cur[i] = 0; }
}

__global__ void scan_kernel() {
    g_off[0] = 0;
    g_off[1] = g_cnt[0];
    g_off[2] = g_cnt[0] + g_cnt[1];
    g_off[3] = g_cnt[0] + g_cnt[1] + g_cnt[2];
}

__global__ void scatter_kernel() {
    int t = blockIdx.x * 256 + threadIdx.x;
    if (t >= T_TOK) return;
    int e = g_sel[t];
    int p = atomicAdd(&g_cur[e], 1);
    g_idx[g_off[e] + p] = t;
}

// ===================== tiled fp32 GEMM (128x128x8) =====================
// mode 0: C = [silu](A @ B + bias), A = Ax (x), C = g_H + coff   (full T rows)
// mode 1: per-expert segments of sorted rows: A = g_H (dh), C = g_do,
//         B/bias indexed by expert (blockIdx.z), row range from g_off.
#define BM 128
#define BN 128
#define BKK 8

__global__ void __launch_bounds__(256)
sgemm_kernel(const float* __restrict__ Ax, const float* __restrict__ Bw,
             const float* __restrict__ bias, int mode, int coff,
             int N, int ldb, long bStride, int biasStride, int doSilu)
{
    __shared__ float As[BKK][BM];
    __shared__ float Bs[BKK][BN];

    const float* A;
    float* C;
    int rowBase, rowEnd;
    const float* Bp = Bw;
    const float* bp = bias;
    if (mode == 0) {
        A = Ax; C = g_H + coff; rowBase = 0; rowEnd = T_TOK;
    } else {
        int e = blockIdx.z;
        A = g_H; C = g_do;
        rowBase = g_off[e]; rowEnd = g_off[e + 1];
        Bp = Bw + (long)e * bStride;
        bp = bias + (long)e * biasStride;
    }
    int blockRow = rowBase + blockIdx.y * BM;
    if (blockRow >= rowEnd) return;
    int vRows = rowEnd - blockRow; if (vRows > BM) vRows = BM;
    int colBase = blockIdx.x * BN;

    int tid  = threadIdx.x;
    int aRow = tid >> 1;
    int aCol = (tid & 1) << 2;
    int bRow = tid >> 5;
    int bCol = (tid & 31) << 2;
    int tx = tid & 15;
    int ty = tid >> 4;

    float acc[8][8];
    #pragma unroll
    for (int i = 0; i < 8; i++)
        #pragma unroll
        for (int j = 0; j < 8; j++) acc[i][j] = 0.f;

    const float* Abase = A + (long)blockRow * DDIM;

    for (int k0 = 0; k0 < DDIM; k0 += BKK) {
        float4 av = make_float4(0.f, 0.f, 0.f, 0.f);
        if (aRow < vRows)
            av = *(const float4*)(Abase + (long)aRow * DDIM + k0 + aCol);
        As[aCol + 0][aRow] = av.x;
        As[aCol + 1][aRow] = av.y;
        As[aCol + 2][aRow] = av.z;
        As[aCol + 3][aRow] = av.w;
        float4 bv = *(const float4*)(Bp + (long)(k0 + bRow) * ldb + colBase + bCol);
        *(float4*)&Bs[bRow][bCol] = bv;
        __syncthreads();
        #pragma unroll
        for (int kk = 0; kk < BKK; kk++) {
            float4 a0 = *(const float4*)&As[kk][ty * 8];
            float4 a1 = *(const float4*)&As[kk][ty * 8 + 4];
            float4 b0 = *(const float4*)&Bs[kk][tx * 8];
            float4 b1 = *(const float4*)&Bs[kk][tx * 8 + 4];
            float ar[8] = {a0.x, a0.y, a0.z, a0.w, a1.x, a1.y, a1.z, a1.w};
            float br[8] = {b0.x, b0.y, b0.z, b0.w, b1.x, b1.y, b1.z, b1.w};
            #pragma unroll
            for (int i = 0; i < 8; i++)
                #pragma unroll
                for (int j = 0; j < 8; j++)
                    acc[i][j] += ar[i] * br[j];
        }
        __syncthreads();
    }

    #pragma unroll
    for (int i = 0; i < 8; i++) {
        int r = ty * 8 + i;
        if (r >= vRows) break;
        float* Crow = C + (long)(blockRow + r) * DDIM + colBase;
        #pragma unroll
        for (int j = 0; j < 8; j++) {
            float v = acc[i][j] + bp[colBase + tx * 8 + j];
            if (doSilu) v = siluf(v);
            Crow[tx * 8 + j] = v;
        }
    }
}

// ===================== heads: logits/argmax + strength =====================
__global__ void __launch_bounds__(256)
heads_kernel(const float* __restrict__ cls_w2, const float* __restrict__ cls_b2,
             const float* __restrict__ var_w2, const float* __restrict__ var_b2)
{
    int t = blockIdx.x;
    const float* h = g_H + (long)t * DDIM;
    float l0 = 0.f, l1 = 0.f, l2 = 0.f, vv = 0.f;
    for (int j = threadIdx.x; j < DHALF; j += 256) {
        float hc = h[j];
        l0 += hc * cls_w2[j * 3 + 0];
        l1 += hc * cls_w2[j * 3 + 1];
        l2 += hc * cls_w2[j * 3 + 2];
        vv += h[DHALF + j] * var_w2[j];
    }
    __shared__ float red[8][4];
    int lane = threadIdx.x & 31, w = threadIdx.x >> 5;
    #pragma unroll
    for (int o = 16; o; o >>= 1) {
        l0 += __shfl_down_sync(0xffffffffu, l0, o);
        l1 += __shfl_down_sync(0xffffffffu, l1, o);
        l2 += __shfl_down_sync(0xffffffffu, l2, o);
        vv += __shfl_down_sync(0xffffffffu, vv, o);
    }
    if (lane == 0) { red[w][0] = l0; red[w][1] = l1; red[w][2] = l2; red[w][3] = vv; }
    __syncthreads();
    if (threadIdx.x == 0) {
        float a0 = 0.f, a1 = 0.f, a2 = 0.f, av = 0.f;
        for (int q = 0; q < 8; q++) { a0 += red[q][0]; a1 += red[q][1]; a2 += red[q][2]; av += red[q][3]; }
        a0 += cls_b2[0]; a1 += cls_b2[1]; a2 += cls_b2[2];
        int best = 0; float bl = a0;
        if (a1 > bl) { bl = a1; best = 1; }
        if (a2 > bl) { bl = a2; best = 2; }
        g_sel[t] = best;
        g_strength[t] = 1.f / (1.f + expf(-(av + var_b2[0])));
        atomicAdd(&g_cnt[best], 1);
    }
}

// ===================== encoder (2 layers) + reparameterization =====================
// 32 tokens per block (gathered by g_idx), expert = blockIdx.z
__global__ void __launch_bounds__(256)
encoder_kernel(const float* __restrict__ x, const float* __restrict__ eps,
               const float* __restrict__ enc_w1, const float* __restrict__ enc_b1,
               const float* __restrict__ enc_w2, const float* __restrict__ enc_b2,
               float* __restrict__ out_noise, float* __restrict__ out_mean,
               float* __restrict__ out_lv)
{
    int e = blockIdx.z;
    int r0 = g_off[e] + blockIdx.x * 32;
    int rEnd = g_off[e + 1];
    if (r0 >= rEnd) return;
    int nt = rEnd - r0; if (nt > 32) nt = 32;

    __shared__ int   tids[32];
    __shared__ float Ash[32][33];
    __shared__ float Hs[32][65];
    __shared__ float Ps[32][129];

    int tid = threadIdx.x;
    if (tid < 32) tids[tid] = (tid < nt) ? g_idx[r0 + tid] : g_idx[r0];
    __syncthreads();

    int tn = tid & 63;     // output n of layer1
    int tg = tid >> 6;     // token group 0..3 (8 tokens each)
    float acc[8];
    #pragma unroll
    for (int j = 0; j < 8; j++) acc[j] = 0.f;
    const float* w1 = enc_w1 + (long)e * DDIM * ND;

    for (int k0 = 0; k0 < DDIM; k0 += 32) {
        {   // stage Ash[32 tokens][32 k]
            int row = tid >> 3;
            int c4  = (tid & 7) << 2;
            const float* xr = x + (long)tids[row] * DDIM + k0 + c4;
            float4 v = *(const float4*)xr;
            Ash[row][c4 + 0] = v.x; Ash[row][c4 + 1] = v.y;
            Ash[row][c4 + 2] = v.z; Ash[row][c4 + 3] = v.w;
        }
        __syncthreads();
        #pragma unroll
        for (int kk = 0; kk < 32; kk++) {
            float w = w1[(long)(k0 + kk) * ND + tn];
            #pragma unroll
            for (int j = 0; j < 8; j++)
                acc[j] += Ash[tg * 8 + j][kk] * w;
        }
        __syncthreads();
    }
    float b1v = enc_b1[e * ND + tn];
    #pragma unroll
    for (int j = 0; j < 8; j++)
        Hs[tg * 8 + j][tn] = siluf(acc[j] + b1v);
    __syncthreads();

    // layer 2: p[32][128]
    int n2 = tid & 127;
    int g2 = tid >> 7;     // 0..1 (16 tokens each)
    float acc2[16];
    #pragma unroll
    for (int j = 0; j < 16; j++) acc2[j] = 0.f;
    const float* w2 = enc_w2 + (long)e * ND * 2 * ND;
    #pragma unroll 4
    for (int k = 0; k < ND; k++) {
        float w = w2[k * 128 + n2];
        #pragma unroll
        for (int j = 0; j < 16; j++)
            acc2[j] += Hs[g2 * 16 + j][k] * w;
    }
    float b2v = enc_b2[e * 128 + n2];
    #pragma unroll
    for (int j = 0; j < 16; j++)
        Ps[g2 * 16 + j][n2] = acc2[j] + b2v;
    __syncthreads();

    // reparameterize + write outputs
    for (int q = tid; q < nt * ND; q += 256) {
        int tok = q >> 6;
        int nd  = q & 63;
        float mean = Ps[tok][nd];
        float lv   = Ps[tok][nd + 64];
        int t = tids[tok];
        float ns = eps[(long)t * ND + nd] * expf(0.5f * lv) + mean;
        out_mean[(long)t * ND + nd]  = mean;
        out_lv[(long)t * ND + nd]    = lv;
        out_noise[(long)t * ND + nd] = ns;
        g_noise[(long)(r0 + tok) * ND + nd] = ns;
    }
}

// ===================== decoder layer 1 (K=64 thin GEMM) -> dh (silu) =====================
__global__ void __launch_bounds__(256)
dec1_kernel(const float* __restrict__ dec_w1, const float* __restrict__ dec_b1)
{
    int e = blockIdx.z;
    int r0 = g_off[e] + blockIdx.x * 64;
    int rEnd = g_off[e + 1];
    if (r0 >= rEnd) return;
    int nt = rEnd - r0; if (nt > 64) nt = 64;
    int nb = blockIdx.y * 128;

    __shared__ float As[64][65];
    int tid = threadIdx.x;
    #pragma unroll
    for (int p = 0; p < 4; p++) {
        int q = p * 256 + tid;     // float4 index, 1024 total
        int row = q >> 4;
        int c4 = (q & 15) << 2;
        float4 v = make_float4(0.f, 0.f, 0.f, 0.f);
        if (row < nt) v = *(const float4*)(g_noise + (long)(r0 + row) * ND + c4);
        As[row][c4 + 0] = v.x; As[row][c4 + 1] = v.y;
        As[row][c4 + 2] = v.z; As[row][c4 + 3] = v.w;
    }
    __syncthreads();

    int nc = tid & 127;
    int g  = tid >> 7;   // 0..1 -> rows g*32..g*32+31
    float acc[32];
    #pragma unroll
    for (int j = 0; j < 32; j++) acc[j] = 0.f;
    const float* w = dec_w1 + (long)e * ND * DDIM + nb + nc;
    #pragma unroll 4
    for (int k = 0; k < ND; k++) {
        float wv = w[(long)k * DDIM];
        #pragma unroll
        for (int j = 0; j < 32; j++)
            acc[j] += As[g * 32 + j][k] * wv;
    }
    float bv = dec_b1[(long)e * DDIM + nb + nc];
    #pragma unroll
    for (int j = 0; j < 32; j++) {
        int row = g * 32 + j;
        if (row < nt)
            g_H[(long)(r0 + row) * DDIM + nb + nc] = siluf(acc[j] + bv);
    }
}

// ===================== LayerNorm + residual epilogue (scatter to token order) =====================
__global__ void __launch_bounds__(256)
ln_out_kernel(const float* __restrict__ x, const float* __restrict__ ln_g,
              const float* __restrict__ ln_b, float* __restrict__ out)
{
    int r = blockIdx.x;
    int e = (r >= g_off[1]) + (r >= g_off[2]);
    int t = g_idx[r];
    const float* row = g_do + (long)r * DDIM;
    int tid = threadIdx.x;
    int c = tid << 2;

    float4 v0 = *(const float4*)(row + c);
    float4 v1 = *(const float4*)(row + 1024 + c);
    float s1 = v0.x + v0.y + v0.z + v0.w + v1.x + v1.y + v1.z + v1.w;
    float s2 = v0.x * v0.x + v0.y * v0.y + v0.z * v0.z + v0.w * v0.w
             + v1.x * v1.x + v1.y * v1.y + v1.z * v1.z + v1.w * v1.w;

    __shared__ float red[8][2];
    __shared__ float stats[2];
    int lane = tid & 31, w = tid >> 5;
    #pragma unroll
    for (int o = 16; o; o >>= 1) {
        s1 += __shfl_down_sync(0xffffffffu, s1, o);
        s2 += __shfl_down_sync(0xffffffffu, s2, o);
    }
    if (lane == 0) { red[w][0] = s1; red[w][1] = s2; }
    __syncthreads();
    if (tid == 0) {
        float a1 = 0.f, a2 = 0.f;
        for (int q = 0; q < 8; q++) { a1 += red[q][0]; a2 += red[q][1]; }
        float mu = a1 * (1.f / DDIM);
        float var = a2 * (1.f / DDIM) - mu * mu;
        if (var < 0.f) var = 0.f;
        stats[0] = mu;
        stats[1] = rsqrtf(var + LN_EPS);
    }
    __syncthreads();
    float mu = stats[0], rstd = stats[1];
    float s = g_strength[t];

    const float* xr = x + (long)t * DDIM;
    const float* gg = ln_g + (long)e * DDIM;
    const float* bb = ln_b + (long)e * DDIM;
    float* orow = out + (long)t * DDIM;

    float4 xv, gv, bv, ov;
    // first half
    xv = *(const float4*)(xr + c); gv = *(const float4*)(gg + c); bv = *(const float4*)(bb + c);
    ov.x = xv.x + s * ((v0.x - mu) * rstd * gv.x + bv.x);
    ov.y = xv.y + s * ((v0.y - mu) * rstd * gv.y + bv.y);
    ov.z = xv.z + s * ((v0.z - mu) * rstd * gv.z + bv.z);
    ov.w = xv.w + s * ((v0.w - mu) * rstd * gv.w + bv.w);
    *(float4*)(orow + c) = ov;
    // second half
    xv = *(const float4*)(xr + 1024 + c); gv = *(const float4*)(gg + 1024 + c); bv = *(const float4*)(bb + 1024 + c);
    ov.x = xv.x + s * ((v1.x - mu) * rstd * gv.x + bv.x);
    ov.y = xv.y + s * ((v1.y - mu) * rstd * gv.y + bv.y);
    ov.z = xv.z + s * ((v1.z - mu) * rstd * gv.z + bv.z);
    ov.w = xv.w + s * ((v1.w - mu) * rstd * gv.w + bv.w);
    *(float4*)(orow + 1024 + c) = ov;
}

// ===================== launch =====================
extern "C" void kernel_launch(void* const* d_in, const int* in_sizes, int n_in,
                              void* d_out, int out_size)
{
    const float* x       = (const float*)d_in[0];
    const float* eps     = (const float*)d_in[1];
    const float* cls_w1  = (const float*)d_in[2];
    const float* cls_b1  = (const float*)d_in[3];
    const float* cls_w2  = (const float*)d_in[4];
    const float* cls_b2  = (const float*)d_in[5];
    const float* var_w1  = (const float*)d_in[6];
    const float* var_b1  = (const float*)d_in[7];
    const float* var_w2  = (const float*)d_in[8];
    const float* var_b2  = (const float*)d_in[9];
    const float* enc_w1  = (const float*)d_in[10];
    const float* enc_b1  = (const float*)d_in[11];
    const float* enc_w2  = (const float*)d_in[12];
    const float* enc_b2  = (const float*)d_in[13];
    const float* dec_w1  = (const float*)d_in[14];
    const float* dec_b1  = (const float*)d_in[15];
    const float* dec_w2  = (const float*)d_in[16];
    const float* dec_b2  = (const float*)d_in[17];
    const float* ln_g    = (const float*)d_in[18];
    const float* ln_b    = (const float*)d_in[19];

    float* out       = (float*)d_out;
    float* out_noise = out + (size_t)T_TOK * DDIM;
    float* out_mean  = out_noise + (size_t)T_TOK * ND;
    float* out_lv    = out_mean + (size_t)T_TOK * ND;

    init_kernel<<<1, 32>>>();

    // cls & var hidden layers: H[:, :1024] and H[:, 1024:]
    sgemm_kernel<<<dim3(8, 128, 1), 256>>>(x, cls_w1, cls_b1, 0, 0,    1024, 1024, 0, 0, 1);
    sgemm_kernel<<<dim3(8, 128, 1), 256>>>(x, var_w1, var_b1, 0, 1024, 1024, 1024, 0, 0, 1);

    heads_kernel<<<T_TOK, 256>>>(cls_w2, cls_b2, var_w2, var_b2);
    scan_kernel<<<1, 1>>>();
    scatter_kernel<<<64, 256>>>();

    encoder_kernel<<<dim3(512, 1, NE), 256>>>(x, eps, enc_w1, enc_b1, enc_w2, enc_b2,
                                              out_noise, out_mean, out_lv);

    dec1_kernel<<<dim3(256, 16, NE), 256>>>(dec_w1, dec_b1);

    // routed big GEMM: do = dh @ dec_w2[e] + dec_b2[e]
    sgemm_kernel<<<dim3(16, 128, NE), 256>>>(nullptr, dec_w2, dec_b2, 1, 0,
                                             2048, 2048, (long)DDIM * DDIM, DDIM, 0);

    ln_out_kernel<<<T_TOK, 256>>>(x, ln_g, ln_b, out);
}

// round 2
// speedup vs baseline: 1.0155x; 1.0155x over previous
#include <cuda_runtime.h>
#include <math.h>

// Problem constants (B=4, S=4096, D=2048, ND=64, E=3)
#define T_TOK 16384
#define DDIM  2048
#define DHALF 1024
#define ND    64
#define NE    3
#define LN_EPS 1e-5f

// -------- device scratch (no allocation allowed) --------
__device__ float g_H[(size_t)T_TOK * DDIM];     // cls|var hidden, later reused as dh_sorted
__device__ float g_do[(size_t)T_TOK * DDIM];    // decoder pre-LN output (sorted order)
__device__ float g_noise[(size_t)T_TOK * ND];   // noise in sorted order
__device__ float g_strength[T_TOK];
__device__ int   g_sel[T_TOK];
__device__ int   g_idx[T_TOK];                  // sorted position -> original token
__device__ int   g_cnt[NE];
__device__ int   g_cur[NE];
__device__ int   g_off[NE + 1];

__device__ __forceinline__ float siluf(float v) { return v / (1.f + expf(-v)); }

// ===================== init / scan / scatter =====================
__global__ void init_kernel() {
    int i = threadIdx.x;
    if (i < NE) { g_cnt[i] = 0; g_cur[i] = 0; }
}

__global__ void scan_kernel() {
    g_off[0] = 0;
    g_off[1] = g_cnt[0];
    g_off[2] = g_cnt[0] + g_cnt[1];
    g_off[3] = g_cnt[0] + g_cnt[1] + g_cnt[2];
}

__global__ void scatter_kernel() {
    int t = blockIdx.x * 256 + threadIdx.x;
    if (t >= T_TOK) return;
    int e = g_sel[t];
    int p = atomicAdd(&g_cur[e], 1);
    g_idx[g_off[e] + p] = t;
}

// ===================== tiled fp32 GEMM (128x128x8) =====================
// mode 0: C = [silu](A @ B + bias), A = Ax (x), C = g_H + coff   (full T rows)
// mode 1: per-expert segments of sorted rows: A = g_H (dh), C = g_do,
//         B/bias indexed by expert (blockIdx.z), row range from g_off.
#define BM 128
#define BN 128
#define BKK 8

__global__ void __launch_bounds__(256)
sgemm_kernel(const float* __restrict__ Ax, const float* __restrict__ Bw,
             const float* __restrict__ bias, int mode, int coff,
             int N, int ldb, long bStride, int biasStride, int doSilu)
{
    __shared__ float As[BKK][BM];
    __shared__ float Bs[BKK][BN];

    const float* A;
    float* C;
    int rowBase, rowEnd;
    const float* Bp = Bw;
    const float* bp = bias;
    if (mode == 0) {
        A = Ax; C = g_H + coff; rowBase = 0; rowEnd = T_TOK;
    } else {
        int e = blockIdx.z;
        A = g_H; C = g_do;
        rowBase = g_off[e]; rowEnd = g_off[e + 1];
        Bp = Bw + (long)e * bStride;
        bp = bias + (long)e * biasStride;
    }
    int blockRow = rowBase + blockIdx.y * BM;
    if (blockRow >= rowEnd) return;
    int vRows = rowEnd - blockRow; if (vRows > BM) vRows = BM;
    int colBase = blockIdx.x * BN;

    int tid  = threadIdx.x;
    int aRow = tid >> 1;
    int aCol = (tid & 1) << 2;
    int bRow = tid >> 5;
    int bCol = (tid & 31) << 2;
    int tx = tid & 15;
    int ty = tid >> 4;

    float acc[8][8];
    #pragma unroll
    for (int i = 0; i < 8; i++)
        #pragma unroll
        for (int j = 0; j < 8; j++) acc[i][j] = 0.f;

    const float* Abase = A + (long)blockRow * DDIM;

    for (int k0 = 0; k0 < DDIM; k0 += BKK) {
        float4 av = make_float4(0.f, 0.f, 0.f, 0.f);
        if (aRow < vRows)
            av = *(const float4*)(Abase + (long)aRow * DDIM + k0 + aCol);
        As[aCol + 0][aRow] = av.x;
        As[aCol + 1][aRow] = av.y;
        As[aCol + 2][aRow] = av.z;
        As[aCol + 3][aRow] = av.w;
        float4 bv = *(const float4*)(Bp + (long)(k0 + bRow) * ldb + colBase + bCol);
        *(float4*)&Bs[bRow][bCol] = bv;
        __syncthreads();
        #pragma unroll
        for (int kk = 0; kk < BKK; kk++) {
            float4 a0 = *(const float4*)&As[kk][ty * 8];
            float4 a1 = *(const float4*)&As[kk][ty * 8 + 4];
            float4 b0 = *(const float4*)&Bs[kk][tx * 8];
            float4 b1 = *(const float4*)&Bs[kk][tx * 8 + 4];
            float ar[8] = {a0.x, a0.y, a0.z, a0.w, a1.x, a1.y, a1.z, a1.w};
            float br[8] = {b0.x, b0.y, b0.z, b0.w, b1.x, b1.y, b1.z, b1.w};
            #pragma unroll
            for (int i = 0; i < 8; i++)
                #pragma unroll
                for (int j = 0; j < 8; j++)
                    acc[i][j] += ar[i] * br[j];
        }
        __syncthreads();
    }

    #pragma unroll
    for (int i = 0; i < 8; i++) {
        int r = ty * 8 + i;
        if (r >= vRows) break;
        float* Crow = C + (long)(blockRow + r) * DDIM + colBase;
        #pragma unroll
        for (int j = 0; j < 8; j++) {
            float v = acc[i][j] + bp[colBase + tx * 8 + j];
            if (doSilu) v = siluf(v);
            Crow[tx * 8 + j] = v;
        }
    }
}

// ===================== heads: logits/argmax + strength =====================
__global__ void __launch_bounds__(256)
heads_kernel(const float* __restrict__ cls_w2, const float* __restrict__ cls_b2,
             const float* __restrict__ var_w2, const float* __restrict__ var_b2)
{
    int t = blockIdx.x;
    const float* h = g_H + (long)t * DDIM;
    float l0 = 0.f, l1 = 0.f, l2 = 0.f, vv = 0.f;
    for (int j = threadIdx.x; j < DHALF; j += 256) {
        float hc = h[j];
        l0 += hc * cls_w2[j * 3 + 0];
        l1 += hc * cls_w2[j * 3 + 1];
        l2 += hc * cls_w2[j * 3 + 2];
        vv += h[DHALF + j] * var_w2[j];
    }
    __shared__ float red[8][4];
    int lane = threadIdx.x & 31, w = threadIdx.x >> 5;
    #pragma unroll
    for (int o = 16; o; o >>= 1) {
        l0 += __shfl_down_sync(0xffffffffu, l0, o);
        l1 += __shfl_down_sync(0xffffffffu, l1, o);
        l2 += __shfl_down_sync(0xffffffffu, l2, o);
        vv += __shfl_down_sync(0xffffffffu, vv, o);
    }
    if (lane == 0) { red[w][0] = l0; red[w][1] = l1; red[w][2] = l2; red[w][3] = vv; }
    __syncthreads();
    if (threadIdx.x == 0) {
        float a0 = 0.f, a1 = 0.f, a2 = 0.f, av = 0.f;
        for (int q = 0; q < 8; q++) { a0 += red[q][0]; a1 += red[q][1]; a2 += red[q][2]; av += red[q][3]; }
        a0 += cls_b2[0]; a1 += cls_b2[1]; a2 += cls_b2[2];
        int best = 0; float bl = a0;
        if (a1 > bl) { bl = a1; best = 1; }
        if (a2 > bl) { bl = a2; best = 2; }
        g_sel[t] = best;
        g_strength[t] = 1.f / (1.f + expf(-(av + var_b2[0])));
        atomicAdd(&g_cnt[best], 1);
    }
}

// ===================== encoder (2 layers) + reparameterization =====================
// 32 tokens per block (gathered by g_idx), expert = blockIdx.z
__global__ void __launch_bounds__(256)
encoder_kernel(const float* __restrict__ x, const float* __restrict__ eps,
               const float* __restrict__ enc_w1, const float* __restrict__ enc_b1,
               const float* __restrict__ enc_w2, const float* __restrict__ enc_b2,
               float* __restrict__ out_noise, float* __restrict__ out_mean,
               float* __restrict__ out_lv)
{
    int e = blockIdx.z;
    int r0 = g_off[e] + blockIdx.x * 32;
    int rEnd = g_off[e + 1];
    if (r0 >= rEnd) return;
    int nt = rEnd - r0; if (nt > 32) nt = 32;

    __shared__ int   tids[32];
    __shared__ float Ash[32][33];
    __shared__ float Hs[32][65];
    __shared__ float Ps[32][129];

    int tid = threadIdx.x;
    if (tid < 32) tids[tid] = (tid < nt) ? g_idx[r0 + tid] : g_idx[r0];
    __syncthreads();

    int tn = tid & 63;     // output n of layer1
    int tg = tid >> 6;     // token group 0..3 (8 tokens each)
    float acc[8];
    #pragma unroll
    for (int j = 0; j < 8; j++) acc[j] = 0.f;
    const float* w1 = enc_w1 + (long)e * DDIM * ND;

    for (int k0 = 0; k0 < DDIM; k0 += 32) {
        {   // stage Ash[32 tokens][32 k]
            int row = tid >> 3;
            int c4  = (tid & 7) << 2;
            const float* xr = x + (long)tids[row] * DDIM + k0 + c4;
            float4 v = *(const float4*)xr;
            Ash[row][c4 + 0] = v.x; Ash[row][c4 + 1] = v.y;
            Ash[row][c4 + 2] = v.z; Ash[row][c4 + 3] = v.w;
        }
        __syncthreads();
        #pragma unroll
        for (int kk = 0; kk < 32; kk++) {
            float w = w1[(long)(k0 + kk) * ND + tn];
            #pragma unroll
            for (int j = 0; j < 8; j++)
                acc[j] += Ash[tg * 8 + j][kk] * w;
        }
        __syncthreads();
    }
    float b1v = enc_b1[e * ND + tn];
    #pragma unroll
    for (int j = 0; j < 8; j++)
        Hs[tg * 8 + j][tn] = siluf(acc[j] + b1v);
    __syncthreads();

    // layer 2: p[32][128]
    int n2 = tid & 127;
    int g2 = tid >> 7;     // 0..1 (16 tokens each)
    float acc2[16];
    #pragma unroll
    for (int j = 0; j < 16; j++) acc2[j] = 0.f;
    const float* w2 = enc_w2 + (long)e * ND * 2 * ND;
    #pragma unroll 4
    for (int k = 0; k < ND; k++) {
        float w = w2[k * 128 + n2];
        #pragma unroll
        for (int j = 0; j < 16; j++)
            acc2[j] += Hs[g2 * 16 + j][k] * w;
    }
    float b2v = enc_b2[e * 128 + n2];
    #pragma unroll
    for (int j = 0; j < 16; j++)
        Ps[g2 * 16 + j][n2] = acc2[j] + b2v;
    __syncthreads();

    // reparameterize + write outputs
    for (int q = tid; q < nt * ND; q += 256) {
        int tok = q >> 6;
        int nd  = q & 63;
        float mean = Ps[tok][nd];
        float lv   = Ps[tok][nd + 64];
        int t = tids[tok];
        float ns = eps[(long)t * ND + nd] * expf(0.5f * lv) + mean;
        out_mean[(long)t * ND + nd]  = mean;
        out_lv[(long)t * ND + nd]    = lv;
        out_noise[(long)t * ND + nd] = ns;
        g_noise[(long)(r0 + tok) * ND + nd] = ns;
    }
}

// ===================== decoder layer 1 (K=64 thin GEMM) -> dh (silu) =====================
__global__ void __launch_bounds__(256)
dec1_kernel(const float* __restrict__ dec_w1, const float* __restrict__ dec_b1)
{
    int e = blockIdx.z;
    int r0 = g_off[e] + blockIdx.x * 64;
    int rEnd = g_off[e + 1];
    if (r0 >= rEnd) return;
    int nt = rEnd - r0; if (nt > 64) nt = 64;
    int nb = blockIdx.y * 128;

    __shared__ float As[64][65];
    int tid = threadIdx.x;
    #pragma unroll
    for (int p = 0; p < 4; p++) {
        int q = p * 256 + tid;     // float4 index, 1024 total
        int row = q >> 4;
        int c4 = (q & 15) << 2;
        float4 v = make_float4(0.f, 0.f, 0.f, 0.f);
        if (row < nt) v = *(const float4*)(g_noise + (long)(r0 + row) * ND + c4);
        As[row][c4 + 0] = v.x; As[row][c4 + 1] = v.y;
        As[row][c4 + 2] = v.z; As[row][c4 + 3] = v.w;
    }
    __syncthreads();

    int nc = tid & 127;
    int g  = tid >> 7;   // 0..1 -> rows g*32..g*32+31
    float acc[32];
    #pragma unroll
    for (int j = 0; j < 32; j++) acc[j] = 0.f;
    const float* w = dec_w1 + (long)e * ND * DDIM + nb + nc;
    #pragma unroll 4
    for (int k = 0; k < ND; k++) {
        float wv = w[(long)k * DDIM];
        #pragma unroll
        for (int j = 0; j < 32; j++)
            acc[j] += As[g * 32 + j][k] * wv;
    }
    float bv = dec_b1[(long)e * DDIM + nb + nc];
    #pragma unroll
    for (int j = 0; j < 32; j++) {
        int row = g * 32 + j;
        if (row < nt)
            g_H[(long)(r0 + row) * DDIM + nb + nc] = siluf(acc[j] + bv);
    }
}

// ===================== LayerNorm + residual epilogue (scatter to token order) =====================
__global__ void __launch_bounds__(256)
ln_out_kernel(const float* __restrict__ x, const float* __restrict__ ln_g,
              const float* __restrict__ ln_b, float* __restrict__ out)
{
    int r = blockIdx.x;
    int e = (r >= g_off[1]) + (r >= g_off[2]);
    int t = g_idx[r];
    const float* row = g_do + (long)r * DDIM;
    int tid = threadIdx.x;
    int c = tid << 2;

    float4 v0 = *(const float4*)(row + c);
    float4 v1 = *(const float4*)(row + 1024 + c);
    float s1 = v0.x + v0.y + v0.z + v0.w + v1.x + v1.y + v1.z + v1.w;
    float s2 = v0.x * v0.x + v0.y * v0.y + v0.z * v0.z + v0.w * v0.w
             + v1.x * v1.x + v1.y * v1.y + v1.z * v1.z + v1.w * v1.w;

    __shared__ float red[8][2];
    __shared__ float stats[2];
    int lane = tid & 31, w = tid >> 5;
    #pragma unroll
    for (int o = 16; o; o >>= 1) {
        s1 += __shfl_down_sync(0xffffffffu, s1, o);
        s2 += __shfl_down_sync(0xffffffffu, s2, o);
    }
    if (lane == 0) { red[w][0] = s1; red[w][1] = s2; }
    __syncthreads();
    if (tid == 0) {
        float a1 = 0.f, a2 = 0.f;
        for (int q = 0; q < 8; q++) { a1 += red[q][0]; a2 += red[q][1]; }
        float mu = a1 * (1.f / DDIM);
        float var = a2 * (1.f / DDIM) - mu * mu;
        if (var < 0.f) var = 0.f;
        stats[0] = mu;
        stats[1] = rsqrtf(var + LN_EPS);
    }
    __syncthreads();
    float mu = stats[0], rstd = stats[1];
    float s = g_strength[t];

    const float* xr = x + (long)t * DDIM;
    const float* gg = ln_g + (long)e * DDIM;
    const float* bb = ln_b + (long)e * DDIM;
    float* orow = out + (long)t * DDIM;

    float4 xv, gv, bv, ov;
    // first half
    xv = *(const float4*)(xr + c); gv = *(const float4*)(gg + c); bv = *(const float4*)(bb + c);
    ov.x = xv.x + s * ((v0.x - mu) * rstd * gv.x + bv.x);
    ov.y = xv.y + s * ((v0.y - mu) * rstd * gv.y + bv.y);
    ov.z = xv.z + s * ((v0.z - mu) * rstd * gv.z + bv.z);
    ov.w = xv.w + s * ((v0.w - mu) * rstd * gv.w + bv.w);
    *(float4*)(orow + c) = ov;
    // second half
    xv = *(const float4*)(xr + 1024 + c); gv = *(const float4*)(gg + 1024 + c); bv = *(const float4*)(bb + 1024 + c);
    ov.x = xv.x + s * ((v1.x - mu) * rstd * gv.x + bv.x);
    ov.y = xv.y + s * ((v1.y - mu) * rstd * gv.y + bv.y);
    ov.z = xv.z + s * ((v1.z - mu) * rstd * gv.z + bv.z);
    ov.w = xv.w + s * ((v1.w - mu) * rstd * gv.w + bv.w);
    *(float4*)(orow + 1024 + c) = ov;
}

// ===================== launch =====================
extern "C" void kernel_launch(void* const* d_in, const int* in_sizes, int n_in,
                              void* d_out, int out_size)
{
    const float* x       = (const float*)d_in[0];
    const float* eps     = (const float*)d_in[1];
    const float* cls_w1  = (const float*)d_in[2];
    const float* cls_b1  = (const float*)d_in[3];
    const float* cls_w2  = (const float*)d_in[4];
    const float* cls_b2  = (const float*)d_in[5];
    const float* var_w1  = (const float*)d_in[6];
    const float* var_b1  = (const float*)d_in[7];
    const float* var_w2  = (const float*)d_in[8];
    const float* var_b2  = (const float*)d_in[9];
    const float* enc_w1  = (const float*)d_in[10];
    const float* enc_b1  = (const float*)d_in[11];
    const float* enc_w2  = (const float*)d_in[12];
    const float* enc_b2  = (const float*)d_in[13];
    const float* dec_w1  = (const float*)d_in[14];
    const float* dec_b1  = (const float*)d_in[15];
    const float* dec_w2  = (const float*)d_in[16];
    const float* dec_b2  = (const float*)d_in[17];
    const float* ln_g    = (const float*)d_in[18];
    const float* ln_b    = (const float*)d_in[19];

    float* out       = (float*)d_out;
    float* out_noise = out + (size_t)T_TOK * DDIM;
    float* out_mean  = out_noise + (size_t)T_TOK * ND;
    float* out_lv    = out_mean + (size_t)T_TOK * ND;

    init_kernel<<<1, 32>>>();

    // cls & var hidden layers: H[:, :1024] and H[:, 1024:]
    sgemm_kernel<<<dim3(8, 128, 1), 256>>>(x, cls_w1, cls_b1, 0, 0,    1024, 1024, 0, 0, 1);
    sgemm_kernel<<<dim3(8, 128, 1), 256>>>(x, var_w1, var_b1, 0, 1024, 1024, 1024, 0, 0, 1);

    heads_kernel<<<T_TOK, 256>>>(cls_w2, cls_b2, var_w2, var_b2);
    scan_kernel<<<1, 1>>>();
    scatter_kernel<<<64, 256>>>();

    encoder_kernel<<<dim3(512, 1, NE), 256>>>(x, eps, enc_w1, enc_b1, enc_w2, enc_b2,
                                              out_noise, out_mean, out_lv);

    dec1_kernel<<<dim3(256, 16, NE), 256>>>(dec_w1, dec_b1);

    // routed big GEMM: do = dh @ dec_w2[e] + dec_b2[e]
    sgemm_kernel<<<dim3(16, 128, NE), 256>>>(nullptr, dec_w2, dec_b2, 1, 0,
                                             2048, 2048, (long)DDIM * DDIM, DDIM, 0);

    ln_out_kernel<<<T_TOK, 256>>>(x, ln_g, ln_b, out);
}

// round 4
// speedup vs baseline: 1.9125x; 1.8834x over previous
#include <cuda_runtime.h>
#include <cuda_bf16.h>
#include <math.h>
#include <stdint.h>

#define T_TOK 16384
#define DDIM  2048
#define DHALF 1024
#define ND    64
#define NE    3
#define LN_EPS 1e-5f
#define FIXCAP 4096

// mma.sync GEMM tiling
#define BM 128
#define BN 128
#define BK 32
#define NCH (DDIM / BK)          // 64
#define STAGE_B 32768            // Ah8K Al8K Bh8K Bl8K
#define OFF_BH 16384
#define GEMM_SMEM (3 * STAGE_B)  // 98304

// -------- device scratch --------
__device__ float g_H[(size_t)T_TOK * DDIM];
__device__ float g_do[(size_t)T_TOK * DDIM];
__device__ float g_noise[(size_t)T_TOK * ND];
__device__ float g_strength[T_TOK];
__device__ int   g_sel[T_TOK];
__device__ int   g_idx[T_TOK];
__device__ int   g_cnt[NE];
__device__ int   g_cur[NE];
__device__ int   g_off[NE + 1];
__device__ int   g_fix_n;
__device__ int   g_fix[FIXCAP];

__device__ __nv_bfloat16 g_xh[(size_t)T_TOK * DDIM];
__device__ __nv_bfloat16 g_xl[(size_t)T_TOK * DDIM];
__device__ __nv_bfloat16 g_dhh[(size_t)(T_TOK + 256) * DDIM];
__device__ __nv_bfloat16 g_dhl[(size_t)(T_TOK + 256) * DDIM];
__device__ __nv_bfloat16 g_w1h[(size_t)DDIM * DDIM];   // fused cls|var W1^T [n][k]
__device__ __nv_bfloat16 g_w1l[(size_t)DDIM * DDIM];
__device__ __nv_bfloat16 g_w2h[(size_t)NE * DDIM * DDIM];
__device__ __nv_bfloat16 g_w2l[(size_t)NE * DDIM * DDIM];
__device__ float g_b1f[DDIM];

__device__ __forceinline__ float siluf(float v) { return v / (1.f + expf(-v)); }

__device__ __forceinline__ uint32_t smem_u32(const void* p) {
    uint32_t a;
    asm("{ .reg .u64 t; cvta.to.shared.u64 t, %1; cvt.u32.u64 %0, t; }" : "=r"(a) : "l"(p));
    return a;
}
__device__ __forceinline__ void cpa16(uint32_t dst, const void* src) {
    asm volatile("cp.async.cg.shared.global [%0], [%1], 16;" :: "r"(dst), "l"(src) : "memory");
}
__device__ __forceinline__ void ldm4(uint32_t* r, uint32_t addr) {
    asm volatile("ldmatrix.sync.aligned.m8n8.x4.shared.b16 {%0,%1,%2,%3}, [%4];"
        : "=r"(r[0]), "=r"(r[1]), "=r"(r[2]), "=r"(r[3]) : "r"(addr));
}
__device__ __forceinline__ void mma16816(float* c, const uint32_t* a, uint32_t b0, uint32_t b1) {
    asm volatile("mma.sync.aligned.m16n8k16.row.col.f32.bf16.bf16.f32 "
        "{%0,%1,%2,%3}, {%4,%5,%6,%7}, {%8,%9}, {%0,%1,%2,%3};"
        : "+f"(c[0]), "+f"(c[1]), "+f"(c[2]), "+f"(c[3])
        : "r"(a[0]), "r"(a[1]), "r"(a[2]), "r"(a[3]), "r"(b0), "r"(b1));
}
__device__ __forceinline__ uint32_t swz(uint32_t off) { return off ^ ((off >> 3) & 0x30); }

// ---------------- small kernels ----------------
__global__ void init_kernel() {
    int i = threadIdx.x;
    if (i < NE) { g_cnt[i] = 0; g_cur[i] = 0; }
    if (i == 0) g_fix_n = 0;
}
__global__ void scan_kernel() {
    g_off[0] = 0;
    g_off[1] = g_cnt[0];
    g_off[2] = g_cnt[0] + g_cnt[1];
    g_off[3] = g_cnt[0] + g_cnt[1] + g_cnt[2];
}
__global__ void count_kernel() {
    int t = blockIdx.x * 256 + threadIdx.x;
    if (t < T_TOK) atomicAdd(&g_cnt[g_sel[t]], 1);
}
__global__ void scatter_kernel() {
    int t = blockIdx.x * 256 + threadIdx.x;
    if (t >= T_TOK) return;
    int e = g_sel[t];
    int p = atomicAdd(&g_cur[e], 1);
    g_idx[g_off[e] + p] = t;
}

__global__ void __launch_bounds__(256) split_x_kernel(const float* __restrict__ x) {
    size_t i = ((size_t)blockIdx.x * 256 + threadIdx.x) * 4;
    float4 v = *(const float4*)(x + i);
    float vv[4] = {v.x, v.y, v.z, v.w};
    uint32_t hp[2], lp[2];
    #pragma unroll
    for (int q = 0; q < 2; q++) {
        __nv_bfloat16 h0 = __float2bfloat16(vv[q * 2 + 0]);
        __nv_bfloat16 h1 = __float2bfloat16(vv[q * 2 + 1]);
        __nv_bfloat16 l0 = __float2bfloat16(vv[q * 2 + 0] - __bfloat162float(h0));
        __nv_bfloat16 l1 = __float2bfloat16(vv[q * 2 + 1] - __bfloat162float(h1));
        hp[q] = (uint32_t)__bfloat16_as_ushort(h0) | ((uint32_t)__bfloat16_as_ushort(h1) << 16);
        lp[q] = (uint32_t)__bfloat16_as_ushort(l0) | ((uint32_t)__bfloat16_as_ushort(l1) << 16);
    }
    *(uint2*)(g_xh + i) = make_uint2(hp[0], hp[1]);
    *(uint2*)(g_xl + i) = make_uint2(lp[0], lp[1]);
}

__global__ void __launch_bounds__(256)
conv_w1t_kernel(const float* __restrict__ cls_w1, const float* __restrict__ var_w1) {
    __shared__ float tile[32][33];
    int n0 = blockIdx.x * 32, k0 = blockIdx.y * 32;
    int tx = threadIdx.x & 31, ty = threadIdx.x >> 5;
    for (int r = ty; r < 32; r += 8) {
        int k = k0 + r, n = n0 + tx;
        tile[r][tx] = (n < DHALF) ? cls_w1[(size_t)k * DHALF + n]
                                  : var_w1[(size_t)k * DHALF + n - DHALF];
    }
    __syncthreads();
    for (int r = ty; r < 32; r += 8) {
        float v = tile[tx][r];
        __nv_bfloat16 h = __float2bfloat16(v);
        size_t o = (size_t)(n0 + r) * DDIM + k0 + tx;
        g_w1h[o] = h;
        g_w1l[o] = __float2bfloat16(v - __bfloat162float(h));
    }
}

__global__ void __launch_bounds__(256)
conv_w2t_kernel(const float* __restrict__ w2) {
    __shared__ float tile[32][33];
    int e = blockIdx.z;
    int n0 = blockIdx.x * 32, k0 = blockIdx.y * 32;
    int tx = threadIdx.x & 31, ty = threadIdx.x >> 5;
    const float* src = w2 + (size_t)e * DDIM * DDIM;
    for (int r = ty; r < 32; r += 8)
        tile[r][tx] = src[(size_t)(k0 + r) * DDIM + n0 + tx];
    __syncthreads();
    __nv_bfloat16* dh = g_w2h + (size_t)e * DDIM * DDIM;
    __nv_bfloat16* dl = g_w2l + (size_t)e * DDIM * DDIM;
    for (int r = ty; r < 32; r += 8) {
        float v = tile[tx][r];
        __nv_bfloat16 h = __float2bfloat16(v);
        size_t o = (size_t)(n0 + r) * DDIM + k0 + tx;
        dh[o] = h;
        dl[o] = __float2bfloat16(v - __bfloat162float(h));
    }
}

__global__ void bias_fuse_kernel(const float* __restrict__ cls_b1, const float* __restrict__ var_b1) {
    int j = blockIdx.x * 256 + threadIdx.x;
    if (j < DDIM) g_b1f[j] = (j < DHALF) ? cls_b1[j] : var_b1[j - DHALF];
}

// ---------------- mma.sync split-bf16 GEMM ----------------
__global__ void __launch_bounds__(256, 1)
mma_gemm_kernel(int mode, const float* __restrict__ dec_b2)
{
    int colBase = blockIdx.x * BN;
    int rowBase, rowEnd, doSilu;
    const __nv_bfloat16 *Ah, *Al, *Bh, *Bl;
    const float* bp;
    float* C;
    if (mode == 0) {
        rowBase = blockIdx.y * BM; rowEnd = T_TOK;
        Ah = g_xh; Al = g_xl; Bh = g_w1h; Bl = g_w1l;
        bp = g_b1f; C = g_H; doSilu = 1;
    } else {
        int e = blockIdx.z;
        rowEnd = g_off[e + 1];
        rowBase = g_off[e] + blockIdx.y * BM;
        if (rowBase >= rowEnd) return;
        Ah = g_dhh; Al = g_dhl;
        Bh = g_w2h + (size_t)e * DDIM * DDIM;
        Bl = g_w2l + (size_t)e * DDIM * DDIM;
        bp = dec_b2 + e * DDIM; C = g_do; doSilu = 0;
    }

    extern __shared__ char smem[];
    uint32_t sb = smem_u32(smem);
    int tid = threadIdx.x, lane = tid & 31, wid = tid >> 5;
    int wm = (wid & 1) * 64, wn = (wid >> 1) * 32;

    float acc[4][4][4];
    #pragma unroll
    for (int i = 0; i < 4; i++)
        #pragma unroll
        for (int j = 0; j < 4; j++)
            #pragma unroll
            for (int q = 0; q < 4; q++) acc[i][j][q] = 0.f;

    auto load_stage = [&](int ck, int s) {
        uint32_t st = sb + s * STAGE_B;
        int k0 = ck * BK;
        #pragma unroll
        for (int p = 0; p < 8; p++) {
            int q = p * 256 + tid;
            int reg = q >> 9;              // 0:Ah 1:Al 2:Bh 3:Bl
            int idx = q & 511;
            int row = idx >> 2, c = idx & 3;
            uint32_t d = st + reg * 8192 + swz(row * 64 + c * 16);
            const __nv_bfloat16* src = (reg == 0) ? Ah : (reg == 1) ? Al : (reg == 2) ? Bh : Bl;
            size_t go = (reg < 2) ? (size_t)(rowBase + row) * DDIM + k0 + c * 8
                                  : (size_t)(colBase + row) * DDIM + k0 + c * 8;
            cpa16(d, src + go);
        }
        asm volatile("cp.async.commit_group;" ::: "memory");
    };

    load_stage(0, 0);
    load_stage(1, 1);

    int lr = lane & 15, lcb = (lane >> 4) << 4;

    for (int ck = 0; ck < NCH; ck++) {
        if (ck < NCH - 1) asm volatile("cp.async.wait_group 1;" ::: "memory");
        else              asm volatile("cp.async.wait_group 0;" ::: "memory");
        __syncthreads();
        if (ck + 2 < NCH) load_stage(ck + 2, (ck + 2) % 3);

        uint32_t st = sb + (ck % 3) * STAGE_B;
        #pragma unroll
        for (int ks = 0; ks < 2; ks++) {
            int kb = ks * 32;
            uint32_t ah[4][4], al[4][4], bh[2][4], bl[2][4];
            #pragma unroll
            for (int mt = 0; mt < 4; mt++) {
                uint32_t a = st + swz((wm + mt * 16 + lr) * 64 + kb + lcb);
                ldm4(ah[mt], a);
                ldm4(al[mt], a + 8192);
            }
            #pragma unroll
            for (int bt = 0; bt < 2; bt++) {
                uint32_t b = st + OFF_BH + swz((wn + bt * 16 + lr) * 64 + kb + lcb);
                ldm4(bh[bt], b);
                ldm4(bl[bt], b + 8192);
            }
            #pragma unroll
            for (int mt = 0; mt < 4; mt++)
                #pragma unroll
                for (int nt = 0; nt < 4; nt++) {
                    int bt = nt >> 1, ss = nt & 1;
                    mma16816(acc[mt][nt], ah[mt], bh[bt][ss], bh[bt][ss + 2]);
                    mma16816(acc[mt][nt], ah[mt], bl[bt][ss], bl[bt][ss + 2]);
                    mma16816(acc[mt][nt], al[mt], bh[bt][ss], bh[bt][ss + 2]);
                }
        }
    }

    #pragma unroll
    for (int nt = 0; nt < 4; nt++) {
        int cc = colBase + wn + nt * 8 + (lane & 3) * 2;
        float b0 = bp[cc], b1 = bp[cc + 1];
        #pragma unroll
        for (int mt = 0; mt < 4; mt++) {
            int r0 = rowBase + wm + mt * 16 + (lane >> 2);
            float* p = acc[mt][nt];
            if (r0 < rowEnd) {
                float2 v = make_float2(p[0] + b0, p[1] + b1);
                if (doSilu) { v.x = siluf(v.x); v.y = siluf(v.y); }
                *(float2*)(C + (size_t)r0 * DDIM + cc) = v;
            }
            if (r0 + 8 < rowEnd) {
                float2 v = make_float2(p[2] + b0, p[3] + b1);
                if (doSilu) { v.x = siluf(v.x); v.y = siluf(v.y); }
                *(float2*)(C + (size_t)(r0 + 8) * DDIM + cc) = v;
            }
        }
    }
}

// ---------------- heads ----------------
__global__ void __launch_bounds__(256)
heads_kernel(const float* __restrict__ cls_w2, const float* __restrict__ cls_b2,
             const float* __restrict__ var_w2, const float* __restrict__ var_b2)
{
    int t = blockIdx.x;
    const float* h = g_H + (size_t)t * DDIM;
    float l0 = 0.f, l1 = 0.f, l2 = 0.f, vv = 0.f;
    for (int j = threadIdx.x; j < DHALF; j += 256) {
        float hc = h[j];
        l0 += hc * cls_w2[j * 3 + 0];
        l1 += hc * cls_w2[j * 3 + 1];
        l2 += hc * cls_w2[j * 3 + 2];
        vv += h[DHALF + j] * var_w2[j];
    }
    __shared__ float red[8][4];
    int lane = threadIdx.x & 31, w = threadIdx.x >> 5;
    #pragma unroll
    for (int o = 16; o; o >>= 1) {
        l0 += __shfl_down_sync(0xffffffffu, l0, o);
        l1 += __shfl_down_sync(0xffffffffu, l1, o);
        l2 += __shfl_down_sync(0xffffffffu, l2, o);
        vv += __shfl_down_sync(0xffffffffu, vv, o);
    }
    if (lane == 0) { red[w][0] = l0; red[w][1] = l1; red[w][2] = l2; red[w][3] = vv; }
    __syncthreads();
    if (threadIdx.x == 0) {
        float a[3] = {0.f, 0.f, 0.f}; float av = 0.f;
        for (int q = 0; q < 8; q++) { a[0] += red[q][0]; a[1] += red[q][1]; a[2] += red[q][2]; av += red[q][3]; }
        a[0] += cls_b2[0]; a[1] += cls_b2[1]; a[2] += cls_b2[2];
        int best = 0;
        if (a[1] > a[best]) best = 1;
        if (a[2] > a[best]) best = 2;
        float second = -1e30f;
        for (int c = 0; c < 3; c++) if (c != best && a[c] > second) second = a[c];
        g_sel[t] = best;
        g_strength[t] = 1.f / (1.f + expf(-(av + var_b2[0])));
        if (a[best] - second < 2e-4f) {
            int p = atomicAdd(&g_fix_n, 1);
            if (p < FIXCAP) g_fix[p] = t;
        }
    }
}

// exact fp32 recompute of cls logits for near-tie tokens
__global__ void __launch_bounds__(256)
fixup_kernel(const float* __restrict__ x,
             const float* __restrict__ cls_w1, const float* __restrict__ cls_b1,
             const float* __restrict__ cls_w2, const float* __restrict__ cls_b2)
{
    __shared__ float xs[DDIM];
    __shared__ float red[8][3];
    int tid = threadIdx.x;
    int nfix = g_fix_n; if (nfix > FIXCAP) nfix = FIXCAP;
    for (int i = blockIdx.x; i < nfix; i += gridDim.x) {
        int t = g_fix[i];
        for (int k = tid; k < DDIM; k += 256) xs[k] = x[(size_t)t * DDIM + k];
        __syncthreads();
        int n0 = tid * 4;
        float acc[4] = {0.f, 0.f, 0.f, 0.f};
        for (int k = 0; k < DDIM; k++) {
            float xv = xs[k];
            const float* wr = cls_w1 + (size_t)k * DHALF + n0;
            acc[0] += xv * wr[0]; acc[1] += xv * wr[1];
            acc[2] += xv * wr[2]; acc[3] += xv * wr[3];
        }
        float l0 = 0.f, l1 = 0.f, l2 = 0.f;
        #pragma unroll
        for (int j = 0; j < 4; j++) {
            float hv = siluf(acc[j] + cls_b1[n0 + j]);
            l0 += hv * cls_w2[(n0 + j) * 3 + 0];
            l1 += hv * cls_w2[(n0 + j) * 3 + 1];
            l2 += hv * cls_w2[(n0 + j) * 3 + 2];
        }
        int lane = tid & 31, w = tid >> 5;
        #pragma unroll
        for (int o = 16; o; o >>= 1) {
            l0 += __shfl_down_sync(0xffffffffu, l0, o);
            l1 += __shfl_down_sync(0xffffffffu, l1, o);
            l2 += __shfl_down_sync(0xffffffffu, l2, o);
        }
        if (lane == 0) { red[w][0] = l0; red[w][1] = l1; red[w][2] = l2; }
        __syncthreads();
        if (tid == 0) {
            float a0 = cls_b2[0], a1 = cls_b2[1], a2 = cls_b2[2];
            for (int q = 0; q < 8; q++) { a0 += red[q][0]; a1 += red[q][1]; a2 += red[q][2]; }
            int best = 0; float bl = a0;
            if (a1 > bl) { bl = a1; best = 1; }
            if (a2 > bl) { bl = a2; best = 2; }
            g_sel[t] = best;
        }
        __syncthreads();
    }
}

// ---------------- encoder ----------------
__global__ void __launch_bounds__(256)
encoder_kernel(const float* __restrict__ x, const float* __restrict__ eps,
               const float* __restrict__ enc_w1, const float* __restrict__ enc_b1,
               const float* __restrict__ enc_w2, const float* __restrict__ enc_b2,
               float* __restrict__ out_noise, float* __restrict__ out_mean,
               float* __restrict__ out_lv)
{
    int e = blockIdx.z;
    int r0 = g_off[e] + blockIdx.x * 32;
    int rEnd = g_off[e + 1];
    if (r0 >= rEnd) return;
    int nt = rEnd - r0; if (nt > 32) nt = 32;

    __shared__ int   tids[32];
    __shared__ float Ash[32][33];
    __shared__ float Hs[32][65];
    __shared__ float Ps[32][129];

    int tid = threadIdx.x;
    if (tid < 32) tids[tid] = (tid < nt) ? g_idx[r0 + tid] : g_idx[r0];
    __syncthreads();

    int tn = tid & 63;
    int tg = tid >> 6;
    float acc[8];
    #pragma unroll
    for (int j = 0; j < 8; j++) acc[j] = 0.f;
    const float* w1 = enc_w1 + (size_t)e * DDIM * ND;

    for (int k0 = 0; k0 < DDIM; k0 += 32) {
        {
            int row = tid >> 3;
            int c4  = (tid & 7) << 2;
            float4 v = *(const float4*)(x + (size_t)tids[row] * DDIM + k0 + c4);
            Ash[row][c4 + 0] = v.x; Ash[row][c4 + 1] = v.y;
            Ash[row][c4 + 2] = v.z; Ash[row][c4 + 3] = v.w;
        }
        __syncthreads();
        #pragma unroll
        for (int kk = 0; kk < 32; kk++) {
            float w = w1[(size_t)(k0 + kk) * ND + tn];
            #pragma unroll
            for (int j = 0; j < 8; j++)
                acc[j] += Ash[tg * 8 + j][kk] * w;
        }
        __syncthreads();
    }
    float b1v = enc_b1[e * ND + tn];
    #pragma unroll
    for (int j = 0; j < 8; j++)
        Hs[tg * 8 + j][tn] = siluf(acc[j] + b1v);
    __syncthreads();

    int n2 = tid & 127;
    int g2 = tid >> 7;
    float acc2[16];
    #pragma unroll
    for (int j = 0; j < 16; j++) acc2[j] = 0.f;
    const float* w2 = enc_w2 + (size_t)e * ND * 2 * ND;
    #pragma unroll 4
    for (int k = 0; k < ND; k++) {
        float w = w2[k * 128 + n2];
        #pragma unroll
        for (int j = 0; j < 16; j++)
            acc2[j] += Hs[g2 * 16 + j][k] * w;
    }
    float b2v = enc_b2[e * 128 + n2];
    #pragma unroll
    for (int j = 0; j < 16; j++)
        Ps[g2 * 16 + j][n2] = acc2[j] + b2v;
    __syncthreads();

    for (int q = tid; q < nt * ND; q += 256) {
        int tok = q >> 6;
        int nd  = q & 63;
        float mean = Ps[tok][nd];
        float lv   = Ps[tok][nd + 64];
        int t = tids[tok];
        float ns = eps[(size_t)t * ND + nd] * expf(0.5f * lv) + mean;
        out_mean[(size_t)t * ND + nd]  = mean;
        out_lv[(size_t)t * ND + nd]    = lv;
        out_noise[(size_t)t * ND + nd] = ns;
        g_noise[(size_t)(r0 + tok) * ND + nd] = ns;
    }
}

// ---------------- decoder layer 1 -> split bf16 dh ----------------
__global__ void __launch_bounds__(256)
dec1_kernel(const float* __restrict__ dec_w1, const float* __restrict__ dec_b1)
{
    int e = blockIdx.z;
    int r0 = g_off[e] + blockIdx.x * 64;
    int rEnd = g_off[e + 1];
    if (r0 >= rEnd) return;
    int nt = rEnd - r0; if (nt > 64) nt = 64;
    int nb = blockIdx.y * 128;

    __shared__ float As[64][65];
    int tid = threadIdx.x;
    #pragma unroll
    for (int p = 0; p < 4; p++) {
        int q = p * 256 + tid;
        int row = q >> 4;
        int c4 = (q & 15) << 2;
        float4 v = make_float4(0.f, 0.f, 0.f, 0.f);
        if (row < nt) v = *(const float4*)(g_noise + (size_t)(r0 + row) * ND + c4);
        As[row][c4 + 0] = v.x; As[row][c4 + 1] = v.y;
        As[row][c4 + 2] = v.z; As[row][c4 + 3] = v.w;
    }
    __syncthreads();

    int nc = tid & 127;
    int g  = tid >> 7;
    float acc[32];
    #pragma unroll
    for (int j = 0; j < 32; j++) acc[j] = 0.f;
    const float* w = dec_w1 + (size_t)e * ND * DDIM + nb + nc;
    #pragma unroll 4
    for (int k = 0; k < ND; k++) {
        float wv = w[(size_t)k * DDIM];
        #pragma unroll
        for (int j = 0; j < 32; j++)
            acc[j] += As[g * 32 + j][k] * wv;
    }
    float bv = dec_b1[(size_t)e * DDIM + nb + nc];
    #pragma unroll
    for (int j = 0; j < 32; j++) {
        int row = g * 32 + j;
        if (row < nt) {
            float v = siluf(acc[j] + bv);
            __nv_bfloat16 h = __float2bfloat16(v);
            size_t o = (size_t)(r0 + row) * DDIM + nb + nc;
            g_dhh[o] = h;
            g_dhl[o] = __float2bfloat16(v - __bfloat162float(h));
        }
    }
}

// ---------------- LayerNorm + residual epilogue ----------------
__global__ void __launch_bounds__(256)
ln_out_kernel(const float* __restrict__ x, const float* __restrict__ ln_g,
              const float* __restrict__ ln_b, float* __restrict__ out)
{
    int r = blockIdx.x;
    int e = (r >= g_off[1]) + (r >= g_off[2]);
    int t = g_idx[r];
    const float* row = g_do + (size_t)r * DDIM;
    int tid = threadIdx.x;
    int c = tid << 2;

    float4 v0 = *(const float4*)(row + c);
    float4 v1 = *(const float4*)(row + 1024 + c);
    float s1 = v0.x + v0.y + v0.z + v0.w + v1.x + v1.y + v1.z + v1.w;
    float s2 = v0.x * v0.x + v0.y * v0.y + v0.z * v0.z + v0.w * v0.w
             + v1.x * v1.x + v1.y * v1.y + v1.z * v1.z + v1.w * v1.w;

    __shared__ float red[8][2];
    __shared__ float stats[2];
    int lane = tid & 31, w = tid >> 5;
    #pragma unroll
    for (int o = 16; o; o >>= 1) {
        s1 += __shfl_down_sync(0xffffffffu, s1, o);
        s2 += __shfl_down_sync(0xffffffffu, s2, o);
    }
    if (lane == 0) { red[w][0] = s1; red[w][1] = s2; }
    __syncthreads();
    if (tid == 0) {
        float a1 = 0.f, a2 = 0.f;
        for (int q = 0; q < 8; q++) { a1 += red[q][0]; a2 += red[q][1]; }
        float mu = a1 * (1.f / DDIM);
        float var = a2 * (1.f / DDIM) - mu * mu;
        if (var < 0.f) var = 0.f;
        stats[0] = mu;
        stats[1] = rsqrtf(var + LN_EPS);
    }
    __syncthreads();
    float mu = stats[0], rstd = stats[1];
    float s = g_strength[t];

    const float* xr = x + (size_t)t * DDIM;
    const float* gg = ln_g + (size_t)e * DDIM;
    const float* bb = ln_b + (size_t)e * DDIM;
    float* orow = out + (size_t)t * DDIM;

    float4 xv, gv, bv, ov;
    xv = *(const float4*)(xr + c); gv = *(const float4*)(gg + c); bv = *(const float4*)(bb + c);
    ov.x = xv.x + s * ((v0.x - mu) * rstd * gv.x + bv.x);
    ov.y = xv.y + s * ((v0.y - mu) * rstd * gv.y + bv.y);
    ov.z = xv.z + s * ((v0.z - mu) * rstd * gv.z + bv.z);
    ov.w = xv.w + s * ((v0.w - mu) * rstd * gv.w + bv.w);
    *(float4*)(orow + c) = ov;
    xv = *(const float4*)(xr + 1024 + c); gv = *(const float4*)(gg + 1024 + c); bv = *(const float4*)(bb + 1024 + c);
    ov.x = xv.x + s * ((v1.x - mu) * rstd * gv.x + bv.x);
    ov.y = xv.y + s * ((v1.y - mu) * rstd * gv.y + bv.y);
    ov.z = xv.z + s * ((v1.z - mu) * rstd * gv.z + bv.z);
    ov.w = xv.w + s * ((v1.w - mu) * rstd * gv.w + bv.w);
    *(float4*)(orow + 1024 + c) = ov;
}

// ---------------- launch ----------------
extern "C" void kernel_launch(void* const* d_in, const int* in_sizes, int n_in,
                              void* d_out, int out_size)
{
    const float* x       = (const float*)d_in[0];
    const float* eps     = (const float*)d_in[1];
    const float* cls_w1  = (const float*)d_in[2];
    const float* cls_b1  = (const float*)d_in[3];
    const float* cls_w2  = (const float*)d_in[4];
    const float* cls_b2  = (const float*)d_in[5];
    const float* var_w1  = (const float*)d_in[6];
    const float* var_b1  = (const float*)d_in[7];
    const float* var_w2  = (const float*)d_in[8];
    const float* var_b2  = (const float*)d_in[9];
    const float* enc_w1  = (const float*)d_in[10];
    const float* enc_b1  = (const float*)d_in[11];
    const float* enc_w2  = (const float*)d_in[12];
    const float* enc_b2  = (const float*)d_in[13];
    const float* dec_w1  = (const float*)d_in[14];
    const float* dec_b1  = (const float*)d_in[15];
    const float* dec_w2  = (const float*)d_in[16];
    const float* dec_b2  = (const float*)d_in[17];
    const float* ln_g    = (const float*)d_in[18];
    const float* ln_b    = (const float*)d_in[19];

    float* out       = (float*)d_out;
    float* out_noise = out + (size_t)T_TOK * DDIM;
    float* out_mean  = out_noise + (size_t)T_TOK * ND;
    float* out_lv    = out_mean + (size_t)T_TOK * ND;

    cudaFuncSetAttribute(mma_gemm_kernel, cudaFuncAttributeMaxDynamicSharedMemorySize, GEMM_SMEM);

    init_kernel<<<1, 32>>>();
    split_x_kernel<<<(T_TOK * DDIM) / 1024, 256>>>(x);
    conv_w1t_kernel<<<dim3(64, 64), 256>>>(cls_w1, var_w1);
    conv_w2t_kernel<<<dim3(64, 64, NE), 256>>>(dec_w2);
    bias_fuse_kernel<<<8, 256>>>(cls_b1, var_b1);

    // stage 1: H = silu(x @ [cls_w1|var_w1] + b)
    mma_gemm_kernel<<<dim3(DDIM / BN, T_TOK / BM, 1), 256, GEMM_SMEM>>>(0, dec_b2);

    heads_kernel<<<T_TOK, 256>>>(cls_w2, cls_b2, var_w2, var_b2);
    fixup_kernel<<<64, 256>>>(x, cls_w1, cls_b1, cls_w2, cls_b2);
    count_kernel<<<T_TOK / 256, 256>>>();
    scan_kernel<<<1, 1>>>();
    scatter_kernel<<<T_TOK / 256, 256>>>();

    encoder_kernel<<<dim3(512, 1, NE), 256>>>(x, eps, enc_w1, enc_b1, enc_w2, enc_b2,
                                              out_noise, out_mean, out_lv);
    dec1_kernel<<<dim3(256, 16, NE), 256>>>(dec_w1, dec_b1);

    // stage 2: do = dh @ dec_w2[e] + dec_b2[e]  (routed, sorted rows)
    mma_gemm_kernel<<<dim3(DDIM / BN, T_TOK / BM, NE), 256, GEMM_SMEM>>>(1, dec_b2);

    ln_out_kernel<<<T_TOK, 256>>>(x, ln_g, ln_b, out);
}

// round 5
// speedup vs baseline: 2.6314x; 1.3759x over previous
#include <cuda_runtime.h>
#include <cuda_fp16.h>
#include <math.h>
#include <stdint.h>

#define T_TOK 16384
#define DDIM  2048
#define DHALF 1024
#define ND    64
#define NE    3
#define LN_EPS 1e-5f
#define FIXCAP 4096

// mma.sync GEMM tiling (fp16 2-term split)
#define BM 128
#define BN 128
#define BK 32
#define NCH (DDIM / BK)          // 64
#define STAGE_B 24576            // Ah 8K | Al 8K | Bh 8K
#define OFF_AL 8192
#define OFF_BH 16384
#define GEMM_SMEM (3 * STAGE_B)  // 73728

// -------- device scratch --------
__device__ float g_H[(size_t)T_TOK * DDIM];
__device__ float g_do[(size_t)T_TOK * DDIM];
__device__ float g_noise[(size_t)T_TOK * ND];
__device__ float g_strength[T_TOK];
__device__ int   g_sel[T_TOK];
__device__ int   g_idx[T_TOK];
__device__ int   g_cnt[NE];
__device__ int   g_cur[NE];
__device__ int   g_off[NE + 1];
__device__ int   g_fix_n;
__device__ int   g_fix[FIXCAP];

__device__ __half g_xh[(size_t)T_TOK * DDIM];
__device__ __half g_xl[(size_t)T_TOK * DDIM];
__device__ __half g_dhh[(size_t)(T_TOK + 256) * DDIM];
__device__ __half g_dhl[(size_t)(T_TOK + 256) * DDIM];
__device__ __half g_w1h[(size_t)DDIM * DDIM];          // fused cls|var W1^T [n][k]
__device__ __half g_w2h[(size_t)NE * DDIM * DDIM];     // dec_w2^T per expert [n][k]
__device__ float g_b1f[DDIM];

__device__ __forceinline__ float siluf(float v) { return v / (1.f + expf(-v)); }

__device__ __forceinline__ uint32_t smem_u32(const void* p) {
    uint32_t a;
    asm("{ .reg .u64 t; cvta.to.shared.u64 t, %1; cvt.u32.u64 %0, t; }" : "=r"(a) : "l"(p));
    return a;
}
__device__ __forceinline__ void cpa16(uint32_t dst, const void* src) {
    asm volatile("cp.async.cg.shared.global [%0], [%1], 16;" :: "r"(dst), "l"(src) : "memory");
}
__device__ __forceinline__ void ldm4(uint32_t* r, uint32_t addr) {
    asm volatile("ldmatrix.sync.aligned.m8n8.x4.shared.b16 {%0,%1,%2,%3}, [%4];"
        : "=r"(r[0]), "=r"(r[1]), "=r"(r[2]), "=r"(r[3]) : "r"(addr));
}
__device__ __forceinline__ void mma16816(float* c, const uint32_t* a, uint32_t b0, uint32_t b1) {
    asm volatile("mma.sync.aligned.m16n8k16.row.col.f32.f16.f16.f32 "
        "{%0,%1,%2,%3}, {%4,%5,%6,%7}, {%8,%9}, {%0,%1,%2,%3};"
        : "+f"(c[0]), "+f"(c[1]), "+f"(c[2]), "+f"(c[3])
        : "r"(a[0]), "r"(a[1]), "r"(a[2]), "r"(a[3]), "r"(b0), "r"(b1));
}
__device__ __forceinline__ uint32_t swz(uint32_t off) { return off ^ ((off >> 3) & 0x30); }

// ---------------- small kernels ----------------
__global__ void init_kernel() {
    int i = threadIdx.x;
    if (i < NE) { g_cnt[i] = 0; g_cur[i] = 0; }
    if (i == 0) g_fix_n = 0;
}
__global__ void scan_kernel() {
    g_off[0] = 0;
    g_off[1] = g_cnt[0];
    g_off[2] = g_cnt[0] + g_cnt[1];
    g_off[3] = g_cnt[0] + g_cnt[1] + g_cnt[2];
}
__global__ void count_kernel() {
    int t = blockIdx.x * 256 + threadIdx.x;
    if (t < T_TOK) atomicAdd(&g_cnt[g_sel[t]], 1);
}
__global__ void scatter_kernel() {
    int t = blockIdx.x * 256 + threadIdx.x;
    if (t >= T_TOK) return;
    int e = g_sel[t];
    int p = atomicAdd(&g_cur[e], 1);
    g_idx[g_off[e] + p] = t;
}

__global__ void __launch_bounds__(256) split_x_kernel(const float* __restrict__ x) {
    size_t i = ((size_t)blockIdx.x * 256 + threadIdx.x) * 4;
    float4 v = *(const float4*)(x + i);
    float vv[4] = {v.x, v.y, v.z, v.w};
    uint32_t hp[2], lp[2];
    #pragma unroll
    for (int q = 0; q < 2; q++) {
        __half h0 = __float2half_rn(vv[q * 2 + 0]);
        __half h1 = __float2half_rn(vv[q * 2 + 1]);
        __half l0 = __float2half_rn(vv[q * 2 + 0] - __half2float(h0));
        __half l1 = __float2half_rn(vv[q * 2 + 1] - __half2float(h1));
        hp[q] = (uint32_t)__half_as_ushort(h0) | ((uint32_t)__half_as_ushort(h1) << 16);
        lp[q] = (uint32_t)__half_as_ushort(l0) | ((uint32_t)__half_as_ushort(l1) << 16);
    }
    *(uint2*)(g_xh + i) = make_uint2(hp[0], hp[1]);
    *(uint2*)(g_xl + i) = make_uint2(lp[0], lp[1]);
}

__global__ void __launch_bounds__(256)
conv_w1t_kernel(const float* __restrict__ cls_w1, const float* __restrict__ var_w1) {
    __shared__ float tile[32][33];
    int n0 = blockIdx.x * 32, k0 = blockIdx.y * 32;
    int tx = threadIdx.x & 31, ty = threadIdx.x >> 5;
    for (int r = ty; r < 32; r += 8) {
        int k = k0 + r, n = n0 + tx;
        tile[r][tx] = (n < DHALF) ? cls_w1[(size_t)k * DHALF + n]
                                  : var_w1[(size_t)k * DHALF + n - DHALF];
    }
    __syncthreads();
    for (int r = ty; r < 32; r += 8)
        g_w1h[(size_t)(n0 + r) * DDIM + k0 + tx] = __float2half_rn(tile[tx][r]);
}

__global__ void __launch_bounds__(256)
conv_w2t_kernel(const float* __restrict__ w2) {
    __shared__ float tile[32][33];
    int e = blockIdx.z;
    int n0 = blockIdx.x * 32, k0 = blockIdx.y * 32;
    int tx = threadIdx.x & 31, ty = threadIdx.x >> 5;
    const float* src = w2 + (size_t)e * DDIM * DDIM;
    for (int r = ty; r < 32; r += 8)
        tile[r][tx] = src[(size_t)(k0 + r) * DDIM + n0 + tx];
    __syncthreads();
    __half* dh = g_w2h + (size_t)e * DDIM * DDIM;
    for (int r = ty; r < 32; r += 8)
        dh[(size_t)(n0 + r) * DDIM + k0 + tx] = __float2half_rn(tile[tx][r]);
}

__global__ void bias_fuse_kernel(const float* __restrict__ cls_b1, const float* __restrict__ var_b1) {
    int j = blockIdx.x * 256 + threadIdx.x;
    if (j < DDIM) g_b1f[j] = (j < DHALF) ? cls_b1[j] : var_b1[j - DHALF];
}

// ---------------- mma.sync fp16 2-term split GEMM ----------------
__global__ void __launch_bounds__(256, 1)
mma_gemm_kernel(int mode, const float* __restrict__ dec_b2)
{
    int colBase = blockIdx.x * BN;
    int rowBase, rowEnd, doSilu;
    const __half *Ah, *Al, *Bh;
    const float* bp;
    float* C;
    if (mode == 0) {
        rowBase = blockIdx.y * BM; rowEnd = T_TOK;
        Ah = g_xh; Al = g_xl; Bh = g_w1h;
        bp = g_b1f; C = g_H; doSilu = 1;
    } else {
        int e = blockIdx.z;
        rowEnd = g_off[e + 1];
        rowBase = g_off[e] + blockIdx.y * BM;
        if (rowBase >= rowEnd) return;
        Ah = g_dhh; Al = g_dhl;
        Bh = g_w2h + (size_t)e * DDIM * DDIM;
        bp = dec_b2 + e * DDIM; C = g_do; doSilu = 0;
    }

    extern __shared__ char smem[];
    uint32_t sb = smem_u32(smem);
    int tid = threadIdx.x, lane = tid & 31, wid = tid >> 5;
    int wm = (wid & 1) * 64, wn = (wid >> 1) * 32;

    float acc[4][4][4];
    #pragma unroll
    for (int i = 0; i < 4; i++)
        #pragma unroll
        for (int j = 0; j < 4; j++)
            #pragma unroll
            for (int q = 0; q < 4; q++) acc[i][j][q] = 0.f;

    auto load_stage = [&](int ck, int s) {
        uint32_t st = sb + s * STAGE_B;
        int k0 = ck * BK;
        #pragma unroll
        for (int p = 0; p < 6; p++) {
            int q = p * 256 + tid;
            int reg = q >> 9;              // 0:Ah 1:Al 2:Bh
            int idx = q & 511;
            int row = idx >> 2, c = idx & 3;
            uint32_t d = st + reg * 8192 + swz(row * 64 + c * 16);
            const __half* src = (reg == 0) ? Ah : (reg == 1) ? Al : Bh;
            size_t go = (reg < 2) ? (size_t)(rowBase + row) * DDIM + k0 + c * 8
                                  : (size_t)(colBase + row) * DDIM + k0 + c * 8;
            cpa16(d, src + go);
        }
        asm volatile("cp.async.commit_group;" ::: "memory");
    };

    load_stage(0, 0);
    load_stage(1, 1);

    int lr = lane & 15, lcb = (lane >> 4) << 4;

    for (int ck = 0; ck < NCH; ck++) {
        if (ck < NCH - 1) asm volatile("cp.async.wait_group 1;" ::: "memory");
        else              asm volatile("cp.async.wait_group 0;" ::: "memory");
        __syncthreads();
        if (ck + 2 < NCH) load_stage(ck + 2, (ck + 2) % 3);

        uint32_t st = sb + (ck % 3) * STAGE_B;
        #pragma unroll
        for (int ks = 0; ks < 2; ks++) {
            int kb = ks * 32;
            uint32_t ah[4][4], al[4][4], bh[2][4];
            #pragma unroll
            for (int mt = 0; mt < 4; mt++) {
                uint32_t a = st + swz((wm + mt * 16 + lr) * 64 + kb + lcb);
                ldm4(ah[mt], a);
                ldm4(al[mt], a + OFF_AL);
            }
            #pragma unroll
            for (int bt = 0; bt < 2; bt++) {
                uint32_t b = st + OFF_BH + swz((wn + bt * 16 + lr) * 64 + kb + lcb);
                ldm4(bh[bt], b);
            }
            #pragma unroll
            for (int mt = 0; mt < 4; mt++)
                #pragma unroll
                for (int nt = 0; nt < 4; nt++) {
                    int bt = nt >> 1, ss = nt & 1;
                    mma16816(acc[mt][nt], ah[mt], bh[bt][ss], bh[bt][ss + 2]);
                    mma16816(acc[mt][nt], al[mt], bh[bt][ss], bh[bt][ss + 2]);
                }
        }
    }

    #pragma unroll
    for (int nt = 0; nt < 4; nt++) {
        int cc = colBase + wn + nt * 8 + (lane & 3) * 2;
        float b0 = bp[cc], b1 = bp[cc + 1];
        #pragma unroll
        for (int mt = 0; mt < 4; mt++) {
            int r0 = rowBase + wm + mt * 16 + (lane >> 2);
            float* p = acc[mt][nt];
            if (r0 < rowEnd) {
                float2 v = make_float2(p[0] + b0, p[1] + b1);
                if (doSilu) { v.x = siluf(v.x); v.y = siluf(v.y); }
                *(float2*)(C + (size_t)r0 * DDIM + cc) = v;
            }
            if (r0 + 8 < rowEnd) {
                float2 v = make_float2(p[2] + b0, p[3] + b1);
                if (doSilu) { v.x = siluf(v.x); v.y = siluf(v.y); }
                *(float2*)(C + (size_t)(r0 + 8) * DDIM + cc) = v;
            }
        }
    }
}

// ---------------- heads ----------------
__global__ void __launch_bounds__(256)
heads_kernel(const float* __restrict__ cls_w2, const float* __restrict__ cls_b2,
             const float* __restrict__ var_w2, const float* __restrict__ var_b2)
{
    int t = blockIdx.x;
    const float* h = g_H + (size_t)t * DDIM;
    float l0 = 0.f, l1 = 0.f, l2 = 0.f, vv = 0.f;
    for (int j = threadIdx.x; j < DHALF; j += 256) {
        float hc = h[j];
        l0 += hc * cls_w2[j * 3 + 0];
        l1 += hc * cls_w2[j * 3 + 1];
        l2 += hc * cls_w2[j * 3 + 2];
        vv += h[DHALF + j] * var_w2[j];
    }
    __shared__ float red[8][4];
    int lane = threadIdx.x & 31, w = threadIdx.x >> 5;
    #pragma unroll
    for (int o = 16; o; o >>= 1) {
        l0 += __shfl_down_sync(0xffffffffu, l0, o);
        l1 += __shfl_down_sync(0xffffffffu, l1, o);
        l2 += __shfl_down_sync(0xffffffffu, l2, o);
        vv += __shfl_down_sync(0xffffffffu, vv, o);
    }
    if (lane == 0) { red[w][0] = l0; red[w][1] = l1; red[w][2] = l2; red[w][3] = vv; }
    __syncthreads();
    if (threadIdx.x == 0) {
        float a[3] = {0.f, 0.f, 0.f}; float av = 0.f;
        for (int q = 0; q < 8; q++) { a[0] += red[q][0]; a[1] += red[q][1]; a[2] += red[q][2]; av += red[q][3]; }
        a[0] += cls_b2[0]; a[1] += cls_b2[1]; a[2] += cls_b2[2];
        int best = 0;
        if (a[1] > a[best]) best = 1;
        if (a[2] > a[best]) best = 2;
        float second = -1e30f;
        for (int c = 0; c < 3; c++) if (c != best && a[c] > second) second = a[c];
        g_sel[t] = best;
        g_strength[t] = 1.f / (1.f + expf(-(av + var_b2[0])));
        if (a[best] - second < 1e-3f) {
            int p = atomicAdd(&g_fix_n, 1);
            if (p < FIXCAP) g_fix[p] = t;
        }
    }
}

// exact fp32 recompute of cls logits for near-tie tokens
__global__ void __launch_bounds__(256)
fixup_kernel(const float* __restrict__ x,
             const float* __restrict__ cls_w1, const float* __restrict__ cls_b1,
             const float* __restrict__ cls_w2, const float* __restrict__ cls_b2)
{
    __shared__ float xs[DDIM];
    __shared__ float red[8][3];
    int tid = threadIdx.x;
    int nfix = g_fix_n; if (nfix > FIXCAP) nfix = FIXCAP;
    for (int i = blockIdx.x; i < nfix; i += gridDim.x) {
        int t = g_fix[i];
        for (int k = tid; k < DDIM; k += 256) xs[k] = x[(size_t)t * DDIM + k];
        __syncthreads();
        int n0 = tid * 4;
        float acc[4] = {0.f, 0.f, 0.f, 0.f};
        for (int k = 0; k < DDIM; k++) {
            float xv = xs[k];
            const float* wr = cls_w1 + (size_t)k * DHALF + n0;
            acc[0] += xv * wr[0]; acc[1] += xv * wr[1];
            acc[2] += xv * wr[2]; acc[3] += xv * wr[3];
        }
        float l0 = 0.f, l1 = 0.f, l2 = 0.f;
        #pragma unroll
        for (int j = 0; j < 4; j++) {
            float hv = siluf(acc[j] + cls_b1[n0 + j]);
            l0 += hv * cls_w2[(n0 + j) * 3 + 0];
            l1 += hv * cls_w2[(n0 + j) * 3 + 1];
            l2 += hv * cls_w2[(n0 + j) * 3 + 2];
        }
        int lane = tid & 31, w = tid >> 5;
        #pragma unroll
        for (int o = 16; o; o >>= 1) {
            l0 += __shfl_down_sync(0xffffffffu, l0, o);
            l1 += __shfl_down_sync(0xffffffffu, l1, o);
            l2 += __shfl_down_sync(0xffffffffu, l2, o);
        }
        if (lane == 0) { red[w][0] = l0; red[w][1] = l1; red[w][2] = l2; }
        __syncthreads();
        if (tid == 0) {
            float a0 = cls_b2[0], a1 = cls_b2[1], a2 = cls_b2[2];
            for (int q = 0; q < 8; q++) { a0 += red[q][0]; a1 += red[q][1]; a2 += red[q][2]; }
            int best = 0; float bl = a0;
            if (a1 > bl) { bl = a1; best = 1; }
            if (a2 > bl) { bl = a2; best = 2; }
            g_sel[t] = best;
        }
        __syncthreads();
    }
}

// ---------------- encoder ----------------
__global__ void __launch_bounds__(256)
encoder_kernel(const float* __restrict__ x, const float* __restrict__ eps,
               const float* __restrict__ enc_w1, const float* __restrict__ enc_b1,
               const float* __restrict__ enc_w2, const float* __restrict__ enc_b2,
               float* __restrict__ out_noise, float* __restrict__ out_mean,
               float* __restrict__ out_lv)
{
    int e = blockIdx.z;
    int r0 = g_off[e] + blockIdx.x * 32;
    int rEnd = g_off[e + 1];
    if (r0 >= rEnd) return;
    int nt = rEnd - r0; if (nt > 32) nt = 32;

    __shared__ int   tids[32];
    __shared__ float Ash[32][33];
    __shared__ float Hs[32][65];
    __shared__ float Ps[32][129];

    int tid = threadIdx.x;
    if (tid < 32) tids[tid] = (tid < nt) ? g_idx[r0 + tid] : g_idx[r0];
    __syncthreads();

    int tn = tid & 63;
    int tg = tid >> 6;
    float acc[8];
    #pragma unroll
    for (int j = 0; j < 8; j++) acc[j] = 0.f;
    const float* w1 = enc_w1 + (size_t)e * DDIM * ND;

    for (int k0 = 0; k0 < DDIM; k0 += 32) {
        {
            int row = tid >> 3;
            int c4  = (tid & 7) << 2;
            float4 v = *(const float4*)(x + (size_t)tids[row] * DDIM + k0 + c4);
            Ash[row][c4 + 0] = v.x; Ash[row][c4 + 1] = v.y;
            Ash[row][c4 + 2] = v.z; Ash[row][c4 + 3] = v.w;
        }
        __syncthreads();
        #pragma unroll
        for (int kk = 0; kk < 32; kk++) {
            float w = w1[(size_t)(k0 + kk) * ND + tn];
            #pragma unroll
            for (int j = 0; j < 8; j++)
                acc[j] += Ash[tg * 8 + j][kk] * w;
        }
        __syncthreads();
    }
    float b1v = enc_b1[e * ND + tn];
    #pragma unroll
    for (int j = 0; j < 8; j++)
        Hs[tg * 8 + j][tn] = siluf(acc[j] + b1v);
    __syncthreads();

    int n2 = tid & 127;
    int g2 = tid >> 7;
    float acc2[16];
    #pragma unroll
    for (int j = 0; j < 16; j++) acc2[j] = 0.f;
    const float* w2 = enc_w2 + (size_t)e * ND * 2 * ND;
    #pragma unroll 4
    for (int k = 0; k < ND; k++) {
        float w = w2[k * 128 + n2];
        #pragma unroll
        for (int j = 0; j < 16; j++)
            acc2[j] += Hs[g2 * 16 + j][k] * w;
    }
    float b2v = enc_b2[e * 128 + n2];
    #pragma unroll
    for (int j = 0; j < 16; j++)
        Ps[g2 * 16 + j][n2] = acc2[j] + b2v;
    __syncthreads();

    for (int q = tid; q < nt * ND; q += 256) {
        int tok = q >> 6;
        int nd  = q & 63;
        float mean = Ps[tok][nd];
        float lv   = Ps[tok][nd + 64];
        int t = tids[tok];
        float ns = eps[(size_t)t * ND + nd] * expf(0.5f * lv) + mean;
        out_mean[(size_t)t * ND + nd]  = mean;
        out_lv[(size_t)t * ND + nd]    = lv;
        out_noise[(size_t)t * ND + nd] = ns;
        g_noise[(size_t)(r0 + tok) * ND + nd] = ns;
    }
}

// ---------------- decoder layer 1 -> split fp16 dh ----------------
__global__ void __launch_bounds__(256)
dec1_kernel(const float* __restrict__ dec_w1, const float* __restrict__ dec_b1)
{
    int e = blockIdx.z;
    int r0 = g_off[e] + blockIdx.x * 64;
    int rEnd = g_off[e + 1];
    if (r0 >= rEnd) return;
    int nt = rEnd - r0; if (nt > 64) nt = 64;
    int nb = blockIdx.y * 128;

    __shared__ float As[64][65];
    int tid = threadIdx.x;
    #pragma unroll
    for (int p = 0; p < 4; p++) {
        int q = p * 256 + tid;
        int row = q >> 4;
        int c4 = (q & 15) << 2;
        float4 v = make_float4(0.f, 0.f, 0.f, 0.f);
        if (row < nt) v = *(const float4*)(g_noise + (size_t)(r0 + row) * ND + c4);
        As[row][c4 + 0] = v.x; As[row][c4 + 1] = v.y;
        As[row][c4 + 2] = v.z; As[row][c4 + 3] = v.w;
    }
    __syncthreads();

    int nc = tid & 127;
    int g  = tid >> 7;
    float acc[32];
    #pragma unroll
    for (int j = 0; j < 32; j++) acc[j] = 0.f;
    const float* w = dec_w1 + (size_t)e * ND * DDIM + nb + nc;
    #pragma unroll 4
    for (int k = 0; k < ND; k++) {
        float wv = w[(size_t)k * DDIM];
        #pragma unroll
        for (int j = 0; j < 32; j++)
            acc[j] += As[g * 32 + j][k] * wv;
    }
    float bv = dec_b1[(size_t)e * DDIM + nb + nc];
    #pragma unroll
    for (int j = 0; j < 32; j++) {
        int row = g * 32 + j;
        if (row < nt) {
            float v = siluf(acc[j] + bv);
            __half h = __float2half_rn(v);
            size_t o = (size_t)(r0 + row) * DDIM + nb + nc;
            g_dhh[o] = h;
            g_dhl[o] = __float2half_rn(v - __half2float(h));
        }
    }
}

// ---------------- LayerNorm + residual epilogue ----------------
__global__ void __launch_bounds__(256)
ln_out_kernel(const float* __restrict__ x, const float* __restrict__ ln_g,
              const float* __restrict__ ln_b, float* __restrict__ out)
{
    int r = blockIdx.x;
    int e = (r >= g_off[1]) + (r >= g_off[2]);
    int t = g_idx[r];
    const float* row = g_do + (size_t)r * DDIM;
    int tid = threadIdx.x;
    int c = tid << 2;

    float4 v0 = *(const float4*)(row + c);
    float4 v1 = *(const float4*)(row + 1024 + c);
    float s1 = v0.x + v0.y + v0.z + v0.w + v1.x + v1.y + v1.z + v1.w;
    float s2 = v0.x * v0.x + v0.y * v0.y + v0.z * v0.z + v0.w * v0.w
             + v1.x * v1.x + v1.y * v1.y + v1.z * v1.z + v1.w * v1.w;

    __shared__ float red[8][2];
    __shared__ float stats[2];
    int lane = tid & 31, w = tid >> 5;
    #pragma unroll
    for (int o = 16; o; o >>= 1) {
        s1 += __shfl_down_sync(0xffffffffu, s1, o);
        s2 += __shfl_down_sync(0xffffffffu, s2, o);
    }
    if (lane == 0) { red[w][0] = s1; red[w][1] = s2; }
    __syncthreads();
    if (tid == 0) {
        float a1 = 0.f, a2 = 0.f;
        for (int q = 0; q < 8; q++) { a1 += red[q][0]; a2 += red[q][1]; }
        float mu = a1 * (1.f / DDIM);
        float var = a2 * (1.f / DDIM) - mu * mu;
        if (var < 0.f) var = 0.f;
        stats[0] = mu;
        stats[1] = rsqrtf(var + LN_EPS);
    }
    __syncthreads();
    float mu = stats[0], rstd = stats[1];
    float s = g_strength[t];

    const float* xr = x + (size_t)t * DDIM;
    const float* gg = ln_g + (size_t)e * DDIM;
    const float* bb = ln_b + (size_t)e * DDIM;
    float* orow = out + (size_t)t * DDIM;

    float4 xv, gv, bv, ov;
    xv = *(const float4*)(xr + c); gv = *(const float4*)(gg + c); bv = *(const float4*)(bb + c);
    ov.x = xv.x + s * ((v0.x - mu) * rstd * gv.x + bv.x);
    ov.y = xv.y + s * ((v0.y - mu) * rstd * gv.y + bv.y);
    ov.z = xv.z + s * ((v0.z - mu) * rstd * gv.z + bv.z);
    ov.w = xv.w + s * ((v0.w - mu) * rstd * gv.w + bv.w);
    *(float4*)(orow + c) = ov;
    xv = *(const float4*)(xr + 1024 + c); gv = *(const float4*)(gg + 1024 + c); bv = *(const float4*)(bb + 1024 + c);
    ov.x = xv.x + s * ((v1.x - mu) * rstd * gv.x + bv.x);
    ov.y = xv.y + s * ((v1.y - mu) * rstd * gv.y + bv.y);
    ov.z = xv.z + s * ((v1.z - mu) * rstd * gv.z + bv.z);
    ov.w = xv.w + s * ((v1.w - mu) * rstd * gv.w + bv.w);
    *(float4*)(orow + 1024 + c) = ov;
}

// ---------------- launch ----------------
extern "C" void kernel_launch(void* const* d_in, const int* in_sizes, int n_in,
                              void* d_out, int out_size)
{
    const float* x       = (const float*)d_in[0];
    const float* eps     = (const float*)d_in[1];
    const float* cls_w1  = (const float*)d_in[2];
    const float* cls_b1  = (const float*)d_in[3];
    const float* cls_w2  = (const float*)d_in[4];
    const float* cls_b2  = (const float*)d_in[5];
    const float* var_w1  = (const float*)d_in[6];
    const float* var_b1  = (const float*)d_in[7];
    const float* var_w2  = (const float*)d_in[8];
    const float* var_b2  = (const float*)d_in[9];
    const float* enc_w1  = (const float*)d_in[10];
    const float* enc_b1  = (const float*)d_in[11];
    const float* enc_w2  = (const float*)d_in[12];
    const float* enc_b2  = (const float*)d_in[13];
    const float* dec_w1  = (const float*)d_in[14];
    const float* dec_b1  = (const float*)d_in[15];
    const float* dec_w2  = (const float*)d_in[16];
    const float* dec_b2  = (const float*)d_in[17];
    const float* ln_g    = (const float*)d_in[18];
    const float* ln_b    = (const float*)d_in[19];

    float* out       = (float*)d_out;
    float* out_noise = out + (size_t)T_TOK * DDIM;
    float* out_mean  = out_noise + (size_t)T_TOK * ND;
    float* out_lv    = out_mean + (size_t)T_TOK * ND;

    cudaFuncSetAttribute(mma_gemm_kernel, cudaFuncAttributeMaxDynamicSharedMemorySize, GEMM_SMEM);

    init_kernel<<<1, 32>>>();
    split_x_kernel<<<(T_TOK * DDIM) / 1024, 256>>>(x);
    conv_w1t_kernel<<<dim3(64, 64), 256>>>(cls_w1, var_w1);
    conv_w2t_kernel<<<dim3(64, 64, NE), 256>>>(dec_w2);
    bias_fuse_kernel<<<8, 256>>>(cls_b1, var_b1);

    // stage 1: H = silu(x @ [cls_w1|var_w1] + b)
    mma_gemm_kernel<<<dim3(DDIM / BN, T_TOK / BM, 1), 256, GEMM_SMEM>>>(0, dec_b2);

    heads_kernel<<<T_TOK, 256>>>(cls_w2, cls_b2, var_w2, var_b2);
    fixup_kernel<<<64, 256>>>(x, cls_w1, cls_b1, cls_w2, cls_b2);
    count_kernel<<<T_TOK / 256, 256>>>();
    scan_kernel<<<1, 1>>>();
    scatter_kernel<<<T_TOK / 256, 256>>>();

    encoder_kernel<<<dim3(512, 1, NE), 256>>>(x, eps, enc_w1, enc_b1, enc_w2, enc_b2,
                                              out_noise, out_mean, out_lv);
    dec1_kernel<<<dim3(256, 16, NE), 256>>>(dec_w1, dec_b1);

    // stage 2: do = dh @ dec_w2[e] + dec_b2[e]  (routed, sorted rows)
    mma_gemm_kernel<<<dim3(DDIM / BN, T_TOK / BM, NE), 256, GEMM_SMEM>>>(1, dec_b2);

    ln_out_kernel<<<T_TOK, 256>>>(x, ln_g, ln_b, out);
}